// round 16
// baseline (speedup 1.0000x reference)
#include <cuda_runtime.h>
#include <cstdint>

// Problem constants: G=512, GP=256, keys fit in 24 bits since b==0.
#define NKEYS  (1u << 24)          // 16,777,216 possible parent keys
#define NWORDS (1u << 19)          // bitmap words (32 keys/word)
#define NBLKS  (NWORDS / 1024)     // 512 scan blocks
#define NMAX   4000000

// Scratch (static device globals)
__device__ unsigned g_bitmap[NWORDS];
__device__ unsigned g_wprefix[NWORDS];    // per-word excl popcount prefix (within 1024-word block)
__device__ unsigned g_blocksums[NBLKS];   // 1024-word-block exclusive prefix
__device__ unsigned g_total;              // number of unique keys
__device__ unsigned g_done;               // last-block-done counter (reset each run)
__device__ unsigned g_combined[NMAX];     // (key<<3)|offset per point

__global__ void k_zero_bitmap() {
    unsigned i = blockIdx.x * blockDim.x + threadIdx.x;
    if (i < NWORDS / 4) reinterpret_cast<uint4*>(g_bitmap)[i] = make_uint4(0, 0, 0, 0);
}

// ---------------------------------------------------------------------------
// Pass 1: per point, compute key + child-offset, mark presence bit.
// ---------------------------------------------------------------------------
__global__ void k_build(const int4* __restrict__ coords, int n) {
    int i = blockIdx.x * blockDim.x + threadIdx.x;
    if (i >= n) return;
    int4 c = coords[i];
    unsigned key = (((unsigned)c.x * 256u + (((unsigned)c.y) >> 1)) * 256u
                    + (((unsigned)c.z) >> 1)) * 256u + (((unsigned)c.w) >> 1);
    unsigned off = (((unsigned)c.y & 1u) << 2) | (((unsigned)c.z & 1u) << 1)
                 | ((unsigned)c.w & 1u);
    g_combined[i] = (key << 3) | off;
    atomicOr(&g_bitmap[key >> 5], 1u << (key & 31u));
}

// ---------------------------------------------------------------------------
// Pass 2 (fused): per-1024-word-block exclusive scan of bitmap popcounts;
// the LAST block to finish also scans the 512 block totals and publishes
// g_total (then resets g_done for the next graph replay).
// ---------------------------------------------------------------------------
__global__ __launch_bounds__(1024) void k_scan_words() {
    __shared__ unsigned warp_sums[32];
    __shared__ int is_last;
    unsigned w = blockIdx.x * 1024u + threadIdx.x;
    unsigned c = __popc(g_bitmap[w]);
    unsigned v = c;
    #pragma unroll
    for (int d = 1; d < 32; d <<= 1) {
        unsigned t = __shfl_up_sync(0xFFFFFFFFu, v, d);
        if ((threadIdx.x & 31u) >= (unsigned)d) v += t;
    }
    if ((threadIdx.x & 31u) == 31u) warp_sums[threadIdx.x >> 5] = v;
    __syncthreads();
    if (threadIdx.x < 32) {
        unsigned s = warp_sums[threadIdx.x];
        #pragma unroll
        for (int d = 1; d < 32; d <<= 1) {
            unsigned t = __shfl_up_sync(0xFFFFFFFFu, s, d);
            if (threadIdx.x >= (unsigned)d) s += t;
        }
        warp_sums[threadIdx.x] = s;
    }
    __syncthreads();
    unsigned warp_off = (threadIdx.x >= 32) ? warp_sums[(threadIdx.x >> 5) - 1] : 0u;
    g_wprefix[w] = warp_off + v - c;
    if (threadIdx.x == 1023) g_blocksums[blockIdx.x] = warp_off + v;

    // -- last-block-done: fold the 512-entry block-total scan in here --
    __threadfence();
    __syncthreads();
    if (threadIdx.x == 0) is_last = (atomicAdd(&g_done, 1u) == gridDim.x - 1u);
    __syncthreads();
    if (!is_last) return;

    unsigned bc = (threadIdx.x < NBLKS) ? g_blocksums[threadIdx.x] : 0u;
    unsigned bv = bc;
    #pragma unroll
    for (int d = 1; d < 32; d <<= 1) {
        unsigned t = __shfl_up_sync(0xFFFFFFFFu, bv, d);
        if ((threadIdx.x & 31u) >= (unsigned)d) bv += t;
    }
    if ((threadIdx.x & 31u) == 31u) warp_sums[threadIdx.x >> 5] = bv;
    __syncthreads();
    if (threadIdx.x < 32) {
        unsigned s = warp_sums[threadIdx.x];
        #pragma unroll
        for (int d = 1; d < 32; d <<= 1) {
            unsigned t = __shfl_up_sync(0xFFFFFFFFu, s, d);
            if (threadIdx.x >= (unsigned)d) s += t;
        }
        warp_sums[threadIdx.x] = s;
    }
    __syncthreads();
    unsigned boff = (threadIdx.x >= 32) ? warp_sums[(threadIdx.x >> 5) - 1] : 0u;
    if (threadIdx.x < NBLKS) g_blocksums[threadIdx.x] = boff + bv - bc;
    if (threadIdx.x == NBLKS - 1) g_total = boff + bv;
    __syncthreads();
    if (threadIdx.x == 0) g_done = 0;   // reset for next graph replay
}

// ---------------------------------------------------------------------------
// Pass 3a (per key half): KEY-per-thread coords emit ONLY (coalesced:
// adjacent active lanes write adjacent ranks). Feats zeroing moved to the
// bulk contiguous pass below.
// ---------------------------------------------------------------------------
__global__ void k_coords_half(float4* __restrict__ out_coords, unsigned keybase) {
    unsigned k = keybase + blockIdx.x * blockDim.x + threadIdx.x;
    unsigned w    = k >> 5;
    unsigned bit  = k & 31u;
    unsigned word = g_bitmap[w];
    if (!((word >> bit) & 1u)) return;
    unsigned rank = g_wprefix[w] + g_blocksums[w >> 10]
                  + (unsigned)__popc(word & ((1u << bit) - 1u));
    out_coords[rank] = make_float4((float)(k >> 24), (float)((k >> 16) & 255u),
                                   (float)((k >> 8) & 255u), (float)(k & 255u));
}

// ---------------------------------------------------------------------------
// Pass 3b (per key half): bulk zero of the half's feats rows — the rank
// interval is contiguous: half boundary rank == g_blocksums[NBLKS/2]
// (wprefix is 0 at a scan-block start). Perfectly coalesced 32B/thread.
// Runs IMMEDIATELY before the half's scatter -> exact L2 warming.
// ---------------------------------------------------------------------------
__global__ void k_zero_feats_half(float4* __restrict__ out_feats4, unsigned half) {
    unsigned mid = g_blocksums[NBLKS / 2];
    unsigned lo  = half ? mid : 0u;
    unsigned hi  = half ? g_total : mid;
    const float4 z = make_float4(0.f, 0.f, 0.f, 0.f);
    for (unsigned r = lo + blockIdx.x * blockDim.x + threadIdx.x; r < hi;
         r += gridDim.x * blockDim.x) {
        out_feats4[(size_t)r * 2]     = z;
        out_feats4[(size_t)r * 2 + 1] = z;
    }
}

// ---------------------------------------------------------------------------
// Pass 4 (per key half): predicated scatter; atomics hit the ~57MB
// just-zeroed half -> mostly L2-resident RMW.
// ---------------------------------------------------------------------------
__global__ void k_scatter_half(const float* __restrict__ feats,
                               float* __restrict__ out_feats, int n, unsigned half) {
    int i = blockIdx.x * blockDim.x + threadIdx.x;
    if (i >= n) return;
    unsigned comb = g_combined[i];
    unsigned key  = comb >> 3;
    if ((key >> 23) != half) return;
    unsigned off  = comb & 7u;
    unsigned w    = key >> 5;
    unsigned bit  = key & 31u;
    unsigned word = g_bitmap[w];
    unsigned rank = g_wprefix[w] + g_blocksums[w >> 10]
                  + (unsigned)__popc(word & ((1u << bit) - 1u));
    atomicAdd(&out_feats[(size_t)rank * 8u + off], feats[i]);
}

// ---------------------------------------------------------------------------
// Pass 5: invalid tail rows (rank >= g_total): coords=-1, feats=0.
// Grid-stride starting AT g_total.
// ---------------------------------------------------------------------------
__global__ void k_fill_invalid(float4* __restrict__ out_coords,
                               float4* __restrict__ out_feats4, int n) {
    const float4 z  = make_float4(0.f, 0.f, 0.f, 0.f);
    const float4 m1 = make_float4(-1.f, -1.f, -1.f, -1.f);
    unsigned start = g_total;
    for (unsigned i = start + blockIdx.x * blockDim.x + threadIdx.x; i < (unsigned)n;
         i += gridDim.x * blockDim.x) {
        out_coords[i] = m1;
        out_feats4[(size_t)i * 2]     = z;
        out_feats4[(size_t)i * 2 + 1] = z;
    }
}

extern "C" void kernel_launch(void* const* d_in, const int* in_sizes, int n_in,
                              void* d_out, int out_size) {
    const int4*  coords = (const int4*)d_in[0];
    const float* feats  = (const float*)d_in[1];
    int n = in_sizes[0] / 4;   // N points

    float4* out_coords = (float4*)d_out;
    float*  out_feats  = (float*)((char*)d_out + (size_t)n * 4 * sizeof(float));
    float4* out_feats4 = (float4*)out_feats;

    k_zero_bitmap    <<<((NWORDS / 4) + 255) / 256, 256>>>();
    k_build          <<<(n + 255) / 256, 256>>>(coords, n);
    k_scan_words     <<<NBLKS, 1024>>>();     // fused: also scans block totals
    // Half 0: coords, then bulk-zero feats (warm L2), then scatter into it.
    k_coords_half    <<<(NKEYS / 2) / 256, 256>>>(out_coords, 0u);
    k_zero_feats_half<<<3072, 256>>>(out_feats4, 0u);
    k_scatter_half   <<<(n + 255) / 256, 256>>>(feats, out_feats, n, 0u);
    // Half 1.
    k_coords_half    <<<(NKEYS / 2) / 256, 256>>>(out_coords, 1u << 23);
    k_zero_feats_half<<<3072, 256>>>(out_feats4, 1u);
    k_scatter_half   <<<(n + 255) / 256, 256>>>(feats, out_feats, n, 1u);
    k_fill_invalid   <<<960, 256>>>(out_coords, out_feats4, n);
}

// round 17
// speedup vs baseline: 1.3279x; 1.3279x over previous
#include <cuda_runtime.h>
#include <cstdint>

// Problem constants: G=512, GP=256, keys fit in 24 bits since b==0.
#define NKEYS  (1u << 24)          // 16,777,216 possible parent keys
#define NWORDS (1u << 19)          // bitmap words (32 keys/word)
#define NBLKS  (NWORDS / 1024)     // 512 scan blocks
#define NMAX   4000000
#define TILEW  256                 // bitmap words per emit block (8192 keys)

// Scratch (static device globals)
__device__ unsigned g_bitmap[NWORDS];
__device__ unsigned g_wprefix[NWORDS];    // per-word excl popcount prefix (within 1024-word block)
__device__ unsigned g_blocksums[NBLKS];   // 1024-word-block exclusive prefix
__device__ unsigned g_total;              // number of unique keys
__device__ unsigned g_done;               // last-block-done counter (reset each run)
__device__ unsigned g_combined[NMAX];     // (key<<3)|offset per point

__global__ void k_zero_bitmap() {
    unsigned i = blockIdx.x * blockDim.x + threadIdx.x;
    if (i < NWORDS / 4) reinterpret_cast<uint4*>(g_bitmap)[i] = make_uint4(0, 0, 0, 0);
}

// ---------------------------------------------------------------------------
// Pass 1: per point, compute key + child-offset, mark presence bit.
// ---------------------------------------------------------------------------
__global__ void k_build(const int4* __restrict__ coords, int n) {
    int i = blockIdx.x * blockDim.x + threadIdx.x;
    if (i >= n) return;
    int4 c = coords[i];
    unsigned key = (((unsigned)c.x * 256u + (((unsigned)c.y) >> 1)) * 256u
                    + (((unsigned)c.z) >> 1)) * 256u + (((unsigned)c.w) >> 1);
    unsigned off = (((unsigned)c.y & 1u) << 2) | (((unsigned)c.z & 1u) << 1)
                 | ((unsigned)c.w & 1u);
    g_combined[i] = (key << 3) | off;
    atomicOr(&g_bitmap[key >> 5], 1u << (key & 31u));
}

// ---------------------------------------------------------------------------
// Pass 2 (fused): per-1024-word-block exclusive scan of bitmap popcounts;
// the LAST block to finish also scans the 512 block totals and publishes
// g_total (then resets g_done for the next graph replay).
// ---------------------------------------------------------------------------
__global__ __launch_bounds__(1024) void k_scan_words() {
    __shared__ unsigned warp_sums[32];
    __shared__ int is_last;
    unsigned w = blockIdx.x * 1024u + threadIdx.x;
    unsigned c = __popc(g_bitmap[w]);
    unsigned v = c;
    #pragma unroll
    for (int d = 1; d < 32; d <<= 1) {
        unsigned t = __shfl_up_sync(0xFFFFFFFFu, v, d);
        if ((threadIdx.x & 31u) >= (unsigned)d) v += t;
    }
    if ((threadIdx.x & 31u) == 31u) warp_sums[threadIdx.x >> 5] = v;
    __syncthreads();
    if (threadIdx.x < 32) {
        unsigned s = warp_sums[threadIdx.x];
        #pragma unroll
        for (int d = 1; d < 32; d <<= 1) {
            unsigned t = __shfl_up_sync(0xFFFFFFFFu, s, d);
            if (threadIdx.x >= (unsigned)d) s += t;
        }
        warp_sums[threadIdx.x] = s;
    }
    __syncthreads();
    unsigned warp_off = (threadIdx.x >= 32) ? warp_sums[(threadIdx.x >> 5) - 1] : 0u;
    g_wprefix[w] = warp_off + v - c;
    if (threadIdx.x == 1023) g_blocksums[blockIdx.x] = warp_off + v;

    // -- last-block-done: fold the 512-entry block-total scan in here --
    __threadfence();
    __syncthreads();
    if (threadIdx.x == 0) is_last = (atomicAdd(&g_done, 1u) == gridDim.x - 1u);
    __syncthreads();
    if (!is_last) return;

    unsigned bc = (threadIdx.x < NBLKS) ? g_blocksums[threadIdx.x] : 0u;
    unsigned bv = bc;
    #pragma unroll
    for (int d = 1; d < 32; d <<= 1) {
        unsigned t = __shfl_up_sync(0xFFFFFFFFu, bv, d);
        if ((threadIdx.x & 31u) >= (unsigned)d) bv += t;
    }
    if ((threadIdx.x & 31u) == 31u) warp_sums[threadIdx.x >> 5] = bv;
    __syncthreads();
    if (threadIdx.x < 32) {
        unsigned s = warp_sums[threadIdx.x];
        #pragma unroll
        for (int d = 1; d < 32; d <<= 1) {
            unsigned t = __shfl_up_sync(0xFFFFFFFFu, s, d);
            if (threadIdx.x >= (unsigned)d) s += t;
        }
        warp_sums[threadIdx.x] = s;
    }
    __syncthreads();
    unsigned boff = (threadIdx.x >= 32) ? warp_sums[(threadIdx.x >> 5) - 1] : 0u;
    if (threadIdx.x < NBLKS) g_blocksums[threadIdx.x] = boff + bv - bc;
    if (threadIdx.x == NBLKS - 1) g_total = boff + bv;
    __syncthreads();
    if (threadIdx.x == 0) g_done = 0;   // reset for next graph replay
}

// ---------------------------------------------------------------------------
// Pass 3 (per key half): BLOCK-STAGED emit. Each block owns 256 bitmap words
// (8192 keys, all within one 1024-word scan block, so ranks are contiguous).
// Phase 1: word-per-thread expand set bits -> smem key list at tile-local
// offsets. Phase 2: sweep the compact list; coalesced coords stores AND
// coalesced feats zeroing at consecutive ranks (warms L2 for the scatter).
// ---------------------------------------------------------------------------
__global__ __launch_bounds__(TILEW) void k_emit_half(float4* __restrict__ out_coords,
                                                     float4* __restrict__ out_feats4,
                                                     unsigned wordbase) {
    __shared__ unsigned s_keys[TILEW * 32];   // up to 8192 keys, 32KB
    __shared__ unsigned s_count;
    unsigned w0 = wordbase + blockIdx.x * TILEW;
    unsigned w  = w0 + threadIdx.x;
    unsigned word = g_bitmap[w];
    unsigned pre0 = g_wprefix[w0];            // broadcast load
    unsigned local = g_wprefix[w] - pre0;     // tile-local start (same scan block)
    if (threadIdx.x == TILEW - 1) s_count = local + (unsigned)__popc(word);
    unsigned kb = w << 5;
    while (word) {
        unsigned bit = (unsigned)__ffs(word) - 1u;
        word &= word - 1u;
        s_keys[local++] = kb + bit;
    }
    __syncthreads();
    unsigned cnt = s_count;
    unsigned blockbase = g_blocksums[w0 >> 10] + pre0;
    const float4 z = make_float4(0.f, 0.f, 0.f, 0.f);
    for (unsigned j = threadIdx.x; j < cnt; j += TILEW) {
        unsigned k = s_keys[j];
        unsigned rank = blockbase + j;
        out_coords[rank] = make_float4((float)(k >> 24), (float)((k >> 16) & 255u),
                                       (float)((k >> 8) & 255u), (float)(k & 255u));
        out_feats4[(size_t)rank * 2]     = z;
        out_feats4[(size_t)rank * 2 + 1] = z;
    }
}

// ---------------------------------------------------------------------------
// Pass 4 (per key half): predicated scatter; atomics hit the ~57MB
// just-zeroed half -> mostly L2-resident RMW.
// ---------------------------------------------------------------------------
__global__ void k_scatter_half(const float* __restrict__ feats,
                               float* __restrict__ out_feats, int n, unsigned half) {
    int i = blockIdx.x * blockDim.x + threadIdx.x;
    if (i >= n) return;
    unsigned comb = g_combined[i];
    unsigned key  = comb >> 3;
    if ((key >> 23) != half) return;
    unsigned off  = comb & 7u;
    unsigned w    = key >> 5;
    unsigned bit  = key & 31u;
    unsigned word = g_bitmap[w];
    unsigned rank = g_wprefix[w] + g_blocksums[w >> 10]
                  + (unsigned)__popc(word & ((1u << bit) - 1u));
    atomicAdd(&out_feats[(size_t)rank * 8u + off], feats[i]);
}

// ---------------------------------------------------------------------------
// Pass 5: invalid tail rows (rank >= g_total): coords=-1, feats=0.
// Grid-stride starting AT g_total.
// ---------------------------------------------------------------------------
__global__ void k_fill_invalid(float4* __restrict__ out_coords,
                               float4* __restrict__ out_feats4, int n) {
    const float4 z  = make_float4(0.f, 0.f, 0.f, 0.f);
    const float4 m1 = make_float4(-1.f, -1.f, -1.f, -1.f);
    unsigned start = g_total;
    for (unsigned i = start + blockIdx.x * blockDim.x + threadIdx.x; i < (unsigned)n;
         i += gridDim.x * blockDim.x) {
        out_coords[i] = m1;
        out_feats4[(size_t)i * 2]     = z;
        out_feats4[(size_t)i * 2 + 1] = z;
    }
}

extern "C" void kernel_launch(void* const* d_in, const int* in_sizes, int n_in,
                              void* d_out, int out_size) {
    const int4*  coords = (const int4*)d_in[0];
    const float* feats  = (const float*)d_in[1];
    int n = in_sizes[0] / 4;   // N points

    float4* out_coords = (float4*)d_out;
    float*  out_feats  = (float*)((char*)d_out + (size_t)n * 4 * sizeof(float));
    float4* out_feats4 = (float4*)out_feats;

    k_zero_bitmap <<<((NWORDS / 4) + 255) / 256, 256>>>();
    k_build       <<<(n + 255) / 256, 256>>>(coords, n);
    k_scan_words  <<<NBLKS, 1024>>>();     // fused: also scans block totals
    // Half 0: staged emit (coords + zero feats, warm L2), then scatter.
    k_emit_half   <<<(NWORDS / 2) / TILEW, TILEW>>>(out_coords, out_feats4, 0u);
    k_scatter_half<<<(n + 255) / 256, 256>>>(feats, out_feats, n, 0u);
    // Half 1.
    k_emit_half   <<<(NWORDS / 2) / TILEW, TILEW>>>(out_coords, out_feats4, NWORDS / 2);
    k_scatter_half<<<(n + 255) / 256, 256>>>(feats, out_feats, n, 1u);
    k_fill_invalid<<<960, 256>>>(out_coords, out_feats4, n);
}